// round 13
// baseline (speedup 1.0000x reference)
#include <cuda_runtime.h>
#include <cstdint>

// ---------------------------------------------------------------------------
// MultiHeadedEMA == causal + anti-causal first-order EMA per (head, channel).
//   fwd: u[t] = q*u[t-1] + x[t] ;  rev: u[t] = q*u[t+1] + x[t]
//   out[b,l,d] = sum_h wf[h,d]*uf + wr[h,d]*ur,  w = expansion*reduction*a
// Round-13: two kernels. A (aggregates) is at DRAM roofline - unchanged.
// B: cp.async (LDGSTS) streams the x tile into smem FIRST, overlapping the
// copy with constants + weight loads + windowed lookback; both scans then
// read x from smem. Removes the serialized x-load latency that pinned B.
// ---------------------------------------------------------------------------

constexpr int kB = 2;
constexpr int kL = 2048;
constexpr int kD = 1024;
constexpr int kH = 8;

constexpr int kChunk   = 16;
constexpr int kNChunk  = kL / kChunk;             // 128
constexpr int kCols    = 256;                     // d-columns per block
constexpr int kThreads = 128;                     // 2 cols/thread -> f32x2
constexpr int kDTiles  = kD / kCols;              // 4
constexpr int kBlocks  = kB * kNChunk * kDTiles;  // 1024

// Per-chunk end states (fwd / rev), L2-resident scratch (16 MB).
__device__ __align__(16) float g_sf[kB][kNChunk][kH][kD];
__device__ __align__(16) float g_sr[kB][kNChunk][kH][kD];

using u64 = unsigned long long;

__device__ __forceinline__ u64 pack2(float lo, float hi) {
    u64 r;
    asm("mov.b64 %0, {%1, %2};"
        : "=l"(r) : "r"(__float_as_uint(lo)), "r"(__float_as_uint(hi)));
    return r;
}
__device__ __forceinline__ u64 fma2(u64 a, u64 b, u64 c) {
    u64 r;
    asm("fma.rn.f32x2 %0, %1, %2, %3;" : "=l"(r) : "l"(a), "l"(b), "l"(c));
    return r;
}
__device__ __forceinline__ u64 add2(u64 a, u64 b) {
    u64 r;
    asm("add.rn.f32x2 %0, %1, %2;" : "=l"(r) : "l"(a), "l"(b));
    return r;
}
__device__ __forceinline__ void store_cs(u64* p, u64 v) {
    float2 f;
    f.x = __uint_as_float((unsigned)(v & 0xffffffffull));
    f.y = __uint_as_float((unsigned)(v >> 32));
    __stcs(reinterpret_cast<float2*>(p), f);
}
__device__ __forceinline__ uint32_t smem_u32(const void* p) {
    uint32_t a;
    asm("{ .reg .u64 t; cvta.to.shared.u64 t, %1; cvt.u32.u64 %0, t; }"
        : "=r"(a) : "l"(p));
    return a;
}

// fp32 sigmoid; use sigp(-v) for the (1 - sigmoid(v)) term (no cancellation).
__device__ __forceinline__ float sigp(float v) { return 1.0f / (1.0f + expf(-v)); }

// ---------------------------------------------------------------------------
// Kernel A: per-chunk local scans (zero-init), publish fwd/rev end states.
// x chunk cached in registers; x read from DRAM exactly once. (DRAM roofline)
// ---------------------------------------------------------------------------
__global__ void __launch_bounds__(kThreads)
ema_agg(const float* __restrict__ x,
        const float* __restrict__ al,  const float* __restrict__ da,
        const float* __restrict__ ral, const float* __restrict__ rda)
{
    __shared__ float s_q[2][kH];

    const int tid = threadIdx.x;
    if (tid < 2 * kH) {
        const int dir = tid >= kH;
        const int h   = tid & (kH - 1);
        const float av = dir ? ral[h] : al[h];
        const float dv = dir ? rda[h] : da[h];
        s_q[dir][h] = sigp(-av) * sigp(dv);
    }

    const int blk = blockIdx.x;
    const int dt = blk & (kDTiles - 1);
    const int c  = (blk >> 2) & (kNChunk - 1);
    const int b  = blk >> 9;

    const u64* xs = reinterpret_cast<const u64*>(
        x + ((size_t)b * kL + (size_t)c * kChunk) * kD + dt * kCols) + tid;
    const int d = dt * kCols + 2 * tid;

    u64 xv[kChunk];
#pragma unroll
    for (int i = 0; i < kChunk; ++i) xv[i] = xs[i * (kD / 2)];

    __syncthreads();

    u64 q2[kH], s[kH];
#pragma unroll
    for (int h = 0; h < kH; ++h) {
        float q = s_q[0][h];
        q2[h] = pack2(q, q);
        s[h] = 0ull;
    }
#pragma unroll
    for (int i = 0; i < kChunk; ++i)
#pragma unroll
        for (int h = 0; h < kH; ++h) s[h] = fma2(q2[h], s[h], xv[i]);
#pragma unroll
    for (int h = 0; h < kH; ++h)
        *reinterpret_cast<u64*>(&g_sf[b][c][h][d]) = s[h];

#pragma unroll
    for (int h = 0; h < kH; ++h) {
        float q = s_q[1][h];
        q2[h] = pack2(q, q);
        s[h] = 0ull;
    }
#pragma unroll
    for (int i = kChunk - 1; i >= 0; --i)
#pragma unroll
        for (int h = 0; h < kH; ++h) s[h] = fma2(q2[h], s[h], xv[i]);
#pragma unroll
    for (int h = 0; h < kH; ++h)
        *reinterpret_cast<u64*>(&g_sr[b][c][h][d]) = s[h];
}

// ---------------------------------------------------------------------------
// Kernel B: cp.async x tile -> smem (overlapped with constants, weights,
// lookback), then windowed lookback + seeded rescan + fused output.
// ---------------------------------------------------------------------------
__global__ void __launch_bounds__(kThreads)
ema_out(const float* __restrict__ x,
        const float* __restrict__ ex,  const float* __restrict__ re,
        const float* __restrict__ al,  const float* __restrict__ da,
        const float* __restrict__ ral, const float* __restrict__ rda,
        float* __restrict__ out)
{
    __shared__ u64 sx[kChunk * kThreads];            // 16 KB x tile
    __shared__ u64 acc[kChunk * kThreads];           // 16 KB fwd partials
    __shared__ float s_q[2][kH], s_a[2][kH], s_qc[2][kH];
    __shared__ int s_W[2];

    const int tid = threadIdx.x;
    const int blk = blockIdx.x;
    const int dt = blk & (kDTiles - 1);
    const int c  = (blk >> 2) & (kNChunk - 1);
    const int b  = blk >> 9;

    // ---- 1. stream x tile into smem asynchronously (FIRST, overlaps all) ---
    const float* xbase =
        x + ((size_t)b * kL + (size_t)c * kChunk) * kD + dt * kCols;
    {
        const uint32_t sxa = smem_u32(sx);
#pragma unroll
        for (int j = 0; j < (kChunk * kCols * 4) / (kThreads * 16); ++j) {
            const int idx = j * kThreads + tid;          // 16B packet index
            const int row = idx >> 6;                    // 64 packets per row
            const int col = idx & 63;
            const float* src = xbase + (size_t)row * kD + col * 4;
            asm volatile("cp.async.cg.shared.global [%0], [%1], 16;"
                         :: "r"(sxa + idx * 16), "l"(src));
        }
        asm volatile("cp.async.commit_group;");
    }

    // ---- 2. per-head constants (overlaps the async copy) ------------------
    if (tid < 2 * kH) {
        const int dr = tid >= kH;
        const int h  = tid & (kH - 1);
        const float av = dr ? ral[h] : al[h];
        const float dv = dr ? rda[h] : da[h];
        s_a[dr][h] = sigp(av);
        float q = sigp(-av) * sigp(dv);
        s_q[dr][h] = q;
        float qc = q;
#pragma unroll
        for (int k = 0; k < 4; ++k) qc *= qc;        // q^16
        s_qc[dr][h] = qc;
    }
    __syncthreads();
    if (tid < 2) {
        float m = 0.0f;
#pragma unroll
        for (int h = 0; h < kH; ++h) m = fmaxf(m, s_qc[tid][h]);
        // W = ceil(ln(1e-8)/ln(qcmax)), clamped to full history.
        int W = kNChunk;
        if (m <= 0.0f) W = 0;
        else {
            float lq = logf(m);
            if (lq < -1e-20f) {
                float w = ceilf(-18.4207f / lq);
                W = (w >= (float)kNChunk) ? kNChunk : (int)w;
            }
        }
        s_W[tid] = W;
    }
    __syncthreads();

    const int d = dt * kCols + 2 * tid;
    const int dh = d >> 1;
    const u64* bsf = reinterpret_cast<const u64*>(g_sf) +
                     (size_t)b * kNChunk * kH * (kD / 2) + dh;
    const u64* bsr = reinterpret_cast<const u64*>(g_sr) +
                     (size_t)b * kNChunk * kH * (kD / 2) + dh;

    u64* od = reinterpret_cast<u64*>(
        out + ((size_t)b * kL + (size_t)c * kChunk) * kD + dt * kCols) + tid;

    // ---- 3. fwd weights + fwd lookback (still overlapping the copy) -------
    u64 uF[kH], wF[kH];
    {
        const int Wf = min(s_W[0], c);
        float wk[kH];
#pragma unroll
        for (int h = 0; h < kH; ++h) { uF[h] = 0ull; wk[h] = 1.0f; }
        for (int k = 0; k < Wf; ++k) {
            const u64* row = bsf + (size_t)(c - 1 - k) * kH * (kD / 2);
#pragma unroll
            for (int h = 0; h < kH; ++h) {
                u64 sv = row[h * (kD / 2)];
                uF[h] = fma2(pack2(wk[h], wk[h]), sv, uF[h]);
                wk[h] *= s_qc[0][h];
            }
        }
#pragma unroll
        for (int h = 0; h < kH; ++h) {
            float a = s_a[0][h];
            float e0 = ex[h * kD + d], e1 = ex[h * kD + d + 1];
            float r0 = re[h * kD + d], r1 = re[h * kD + d + 1];
            wF[h] = pack2(e0 * r0 * a, e1 * r1 * a);
        }
    }

    // ---- 4. x tile ready ----------------------------------------------------
    asm volatile("cp.async.wait_group 0;");
    __syncthreads();

    // ---- 5. forward seeded rescan (x from smem) -----------------------------
    {
        u64 q2[kH];
#pragma unroll
        for (int h = 0; h < kH; ++h) {
            float q = s_q[0][h];
            q2[h] = pack2(q, q);
        }
#pragma unroll
        for (int i = 0; i < kChunk; ++i) {
            u64 xv = sx[i * kThreads + tid];
            u64 fs = 0ull;
#pragma unroll
            for (int h = 0; h < kH; ++h) {
                uF[h] = fma2(q2[h], uF[h], xv);
                fs    = fma2(wF[h], uF[h], fs);
            }
            acc[i * kThreads + tid] = fs;
        }
    }

    // ---- 6. reverse: lookback + seeded rescan + fused store -----------------
    {
        const int Wr = min(s_W[1], kNChunk - 1 - c);
        u64 u[kH];
        float wk[kH];
#pragma unroll
        for (int h = 0; h < kH; ++h) { u[h] = 0ull; wk[h] = 1.0f; }
        for (int k = 0; k < Wr; ++k) {
            const u64* row = bsr + (size_t)(c + 1 + k) * kH * (kD / 2);
#pragma unroll
            for (int h = 0; h < kH; ++h) {
                u64 sv = row[h * (kD / 2)];
                u[h] = fma2(pack2(wk[h], wk[h]), sv, u[h]);
                wk[h] *= s_qc[1][h];
            }
        }

        u64 q2[kH], w[kH];
#pragma unroll
        for (int h = 0; h < kH; ++h) {
            float q = s_q[1][h], a = s_a[1][h];
            q2[h] = pack2(q, q);
            float e0 = ex[(kH + h) * kD + d], e1 = ex[(kH + h) * kD + d + 1];
            float r0 = re[(kH + h) * kD + d], r1 = re[(kH + h) * kD + d + 1];
            w[h] = pack2(e0 * r0 * a, e1 * r1 * a);
        }
#pragma unroll
        for (int i = kChunk - 1; i >= 0; --i) {
            u64 xv = sx[i * kThreads + tid];
            u64 rs = 0ull;
#pragma unroll
            for (int h = 0; h < kH; ++h) {
                u[h] = fma2(q2[h], u[h], xv);
                rs   = fma2(w[h], u[h], rs);
            }
            store_cs(od + i * (kD / 2),
                     add2(acc[i * kThreads + tid], rs));  // out written once
        }
    }
}

// ---------------------------------------------------------------------------
extern "C" void kernel_launch(void* const* d_in, const int* in_sizes, int n_in,
                              void* d_out, int out_size)
{
    const float* x   = (const float*)d_in[0];
    const float* ex  = (const float*)d_in[1];
    const float* re  = (const float*)d_in[2];
    const float* al  = (const float*)d_in[3];
    const float* da  = (const float*)d_in[4];
    const float* ral = (const float*)d_in[5];
    const float* rda = (const float*)d_in[6];
    float* out = (float*)d_out;

    ema_agg<<<kBlocks, kThreads>>>(x, al, da, ral, rda);
    ema_out<<<kBlocks, kThreads>>>(x, ex, re, al, da, ral, rda, out);
}

// round 14
// speedup vs baseline: 1.0076x; 1.0076x over previous
#include <cuda_runtime.h>
#include <cstdint>

// ---------------------------------------------------------------------------
// MultiHeadedEMA == causal + anti-causal first-order EMA per (head, channel).
//   fwd: u[t] = q*u[t-1] + x[t] ;  rev: u[t] = q*u[t+1] + x[t]
//   out[b,l,d] = sum_h wf[h,d]*uf + wr[h,d]*ur,  w = expansion*reduction*a
// Round-14: A unchanged (DRAM roofline). B rebuilt A-style: register-batched
// x loads + weight loads issued FIRST, then griddepcontrol.wait. A+B linked
// by Programmatic Dependent Launch so B's whole DRAM prologue overlaps A's
// execution. Lookback gives cross-chunk seeds (geometric truncation @1e-8).
// ---------------------------------------------------------------------------

constexpr int kB = 2;
constexpr int kL = 2048;
constexpr int kD = 1024;
constexpr int kH = 8;

constexpr int kChunk   = 16;
constexpr int kNChunk  = kL / kChunk;             // 128
constexpr int kCols    = 256;                     // d-columns per block
constexpr int kThreads = 128;                     // 2 cols/thread -> f32x2
constexpr int kDTiles  = kD / kCols;              // 4
constexpr int kBlocks  = kB * kNChunk * kDTiles;  // 1024

// Per-chunk end states (fwd / rev), L2-resident scratch (16 MB).
__device__ __align__(16) float g_sf[kB][kNChunk][kH][kD];
__device__ __align__(16) float g_sr[kB][kNChunk][kH][kD];

using u64 = unsigned long long;

__device__ __forceinline__ u64 pack2(float lo, float hi) {
    u64 r;
    asm("mov.b64 %0, {%1, %2};"
        : "=l"(r) : "r"(__float_as_uint(lo)), "r"(__float_as_uint(hi)));
    return r;
}
__device__ __forceinline__ u64 fma2(u64 a, u64 b, u64 c) {
    u64 r;
    asm("fma.rn.f32x2 %0, %1, %2, %3;" : "=l"(r) : "l"(a), "l"(b), "l"(c));
    return r;
}
__device__ __forceinline__ u64 add2(u64 a, u64 b) {
    u64 r;
    asm("add.rn.f32x2 %0, %1, %2;" : "=l"(r) : "l"(a), "l"(b));
    return r;
}
__device__ __forceinline__ void store_cs(u64* p, u64 v) {
    float2 f;
    f.x = __uint_as_float((unsigned)(v & 0xffffffffull));
    f.y = __uint_as_float((unsigned)(v >> 32));
    __stcs(reinterpret_cast<float2*>(p), f);
}

// fp32 sigmoid; use sigp(-v) for the (1 - sigmoid(v)) term (no cancellation).
__device__ __forceinline__ float sigp(float v) { return 1.0f / (1.0f + expf(-v)); }

// ---------------------------------------------------------------------------
// Kernel A: per-chunk local scans (zero-init), publish fwd/rev end states.
// Fires the PDL trigger at entry so kernel B can launch and run its
// independent prologue concurrently.
// ---------------------------------------------------------------------------
__global__ void __launch_bounds__(kThreads)
ema_agg(const float* __restrict__ x,
        const float* __restrict__ al,  const float* __restrict__ da,
        const float* __restrict__ ral, const float* __restrict__ rda)
{
    asm volatile("griddepcontrol.launch_dependents;");

    __shared__ float s_q[2][kH];

    const int tid = threadIdx.x;
    if (tid < 2 * kH) {
        const int dir = tid >= kH;
        const int h   = tid & (kH - 1);
        const float av = dir ? ral[h] : al[h];
        const float dv = dir ? rda[h] : da[h];
        s_q[dir][h] = sigp(-av) * sigp(dv);
    }

    const int blk = blockIdx.x;
    const int dt = blk & (kDTiles - 1);
    const int c  = (blk >> 2) & (kNChunk - 1);
    const int b  = blk >> 9;

    const u64* xs = reinterpret_cast<const u64*>(
        x + ((size_t)b * kL + (size_t)c * kChunk) * kD + dt * kCols) + tid;
    const int d = dt * kCols + 2 * tid;

    u64 xv[kChunk];
#pragma unroll
    for (int i = 0; i < kChunk; ++i) xv[i] = xs[i * (kD / 2)];

    __syncthreads();

    u64 q2[kH], s[kH];
#pragma unroll
    for (int h = 0; h < kH; ++h) {
        float q = s_q[0][h];
        q2[h] = pack2(q, q);
        s[h] = 0ull;
    }
#pragma unroll
    for (int i = 0; i < kChunk; ++i)
#pragma unroll
        for (int h = 0; h < kH; ++h) s[h] = fma2(q2[h], s[h], xv[i]);
#pragma unroll
    for (int h = 0; h < kH; ++h)
        *reinterpret_cast<u64*>(&g_sf[b][c][h][d]) = s[h];

#pragma unroll
    for (int h = 0; h < kH; ++h) {
        float q = s_q[1][h];
        q2[h] = pack2(q, q);
        s[h] = 0ull;
    }
#pragma unroll
    for (int i = kChunk - 1; i >= 0; --i)
#pragma unroll
        for (int h = 0; h < kH; ++h) s[h] = fma2(q2[h], s[h], xv[i]);
#pragma unroll
    for (int h = 0; h < kH; ++h)
        *reinterpret_cast<u64*>(&g_sr[b][c][h][d]) = s[h];
}

// ---------------------------------------------------------------------------
// Kernel B: register-batched x + weight loads FIRST (overlap kernel A via
// PDL), griddepcontrol.wait, then windowed lookback + seeded rescans +
// fused output (written once, streaming).
// ---------------------------------------------------------------------------
__global__ void __launch_bounds__(kThreads)
ema_out(const float* __restrict__ x,
        const float* __restrict__ ex,  const float* __restrict__ re,
        const float* __restrict__ al,  const float* __restrict__ da,
        const float* __restrict__ ral, const float* __restrict__ rda,
        float* __restrict__ out)
{
    __shared__ u64 acc[kChunk * kThreads];           // 16 KB fwd partials
    __shared__ float s_q[2][kH], s_a[2][kH], s_qc[2][kH];
    __shared__ int s_W[2];

    const int tid = threadIdx.x;
    const int blk = blockIdx.x;
    const int dt = blk & (kDTiles - 1);
    const int c  = (blk >> 2) & (kNChunk - 1);
    const int b  = blk >> 9;

    const u64* xs = reinterpret_cast<const u64*>(
        x + ((size_t)b * kL + (size_t)c * kChunk) * kD + dt * kCols) + tid;
    const int d = dt * kCols + 2 * tid;

    // ---- 1. x tile: 16 batched loads, first instructions (overlap A) ------
    u64 xv[kChunk];
#pragma unroll
    for (int i = 0; i < kChunk; ++i) xv[i] = xs[i * (kD / 2)];

    // ---- 2. weight loads, both directions (independent of A) --------------
    float e0f[kH], e1f[kH], r0f[kH], r1f[kH];
    float e0r[kH], e1r[kH], r0r[kH], r1r[kH];
#pragma unroll
    for (int h = 0; h < kH; ++h) {
        e0f[h] = ex[h * kD + d];        e1f[h] = ex[h * kD + d + 1];
        r0f[h] = re[h * kD + d];        r1f[h] = re[h * kD + d + 1];
        e0r[h] = ex[(kH + h) * kD + d]; e1r[h] = ex[(kH + h) * kD + d + 1];
        r0r[h] = re[(kH + h) * kD + d]; r1r[h] = re[(kH + h) * kD + d + 1];
    }

    // ---- 3. per-head constants ---------------------------------------------
    if (tid < 2 * kH) {
        const int dr = tid >= kH;
        const int h  = tid & (kH - 1);
        const float av = dr ? ral[h] : al[h];
        const float dv = dr ? rda[h] : da[h];
        s_a[dr][h] = sigp(av);
        float q = sigp(-av) * sigp(dv);
        s_q[dr][h] = q;
        float qc = q;
#pragma unroll
        for (int k = 0; k < 4; ++k) qc *= qc;        // q^16
        s_qc[dr][h] = qc;
    }
    __syncthreads();
    if (tid < 2) {
        float m = 0.0f;
#pragma unroll
        for (int h = 0; h < kH; ++h) m = fmaxf(m, s_qc[tid][h]);
        // W = ceil(ln(1e-8)/ln(qcmax)), clamped to full history.
        int W = kNChunk;
        if (m <= 0.0f) W = 0;
        else {
            float lq = logf(m);
            if (lq < -1e-20f) {
                float w = ceilf(-18.4207f / lq);
                W = (w >= (float)kNChunk) ? kNChunk : (int)w;
            }
        }
        s_W[tid] = W;
    }
    __syncthreads();

    // ---- 4. wait for kernel A's aggregates ---------------------------------
    asm volatile("griddepcontrol.wait;");

    const int dh = d >> 1;
    const u64* bsf = reinterpret_cast<const u64*>(g_sf) +
                     (size_t)b * kNChunk * kH * (kD / 2) + dh;
    const u64* bsr = reinterpret_cast<const u64*>(g_sr) +
                     (size_t)b * kNChunk * kH * (kD / 2) + dh;

    u64* od = reinterpret_cast<u64*>(
        out + ((size_t)b * kL + (size_t)c * kChunk) * kD + dt * kCols) + tid;

    // ---- 5. forward: lookback prefix + seeded rescan -----------------------
    {
        const int Wf = min(s_W[0], c);
        u64 u[kH];
        float wk[kH];
#pragma unroll
        for (int h = 0; h < kH; ++h) { u[h] = 0ull; wk[h] = 1.0f; }
        for (int k = 0; k < Wf; ++k) {
            const u64* row = bsf + (size_t)(c - 1 - k) * kH * (kD / 2);
#pragma unroll
            for (int h = 0; h < kH; ++h) {
                u64 sv = row[h * (kD / 2)];
                u[h] = fma2(pack2(wk[h], wk[h]), sv, u[h]);
                wk[h] *= s_qc[0][h];
            }
        }

        u64 q2[kH], w[kH];
#pragma unroll
        for (int h = 0; h < kH; ++h) {
            float q = s_q[0][h], a = s_a[0][h];
            q2[h] = pack2(q, q);
            w[h] = pack2(e0f[h] * r0f[h] * a, e1f[h] * r1f[h] * a);
        }
#pragma unroll
        for (int i = 0; i < kChunk; ++i) {
            u64 fs = 0ull;
#pragma unroll
            for (int h = 0; h < kH; ++h) {
                u[h] = fma2(q2[h], u[h], xv[i]);
                fs   = fma2(w[h], u[h], fs);
            }
            acc[i * kThreads + tid] = fs;
        }
    }

    // ---- 6. reverse: lookback prefix + seeded rescan + fused store ---------
    {
        const int Wr = min(s_W[1], kNChunk - 1 - c);
        u64 u[kH];
        float wk[kH];
#pragma unroll
        for (int h = 0; h < kH; ++h) { u[h] = 0ull; wk[h] = 1.0f; }
        for (int k = 0; k < Wr; ++k) {
            const u64* row = bsr + (size_t)(c + 1 + k) * kH * (kD / 2);
#pragma unroll
            for (int h = 0; h < kH; ++h) {
                u64 sv = row[h * (kD / 2)];
                u[h] = fma2(pack2(wk[h], wk[h]), sv, u[h]);
                wk[h] *= s_qc[1][h];
            }
        }

        u64 q2[kH], w[kH];
#pragma unroll
        for (int h = 0; h < kH; ++h) {
            float q = s_q[1][h], a = s_a[1][h];
            q2[h] = pack2(q, q);
            w[h] = pack2(e0r[h] * r0r[h] * a, e1r[h] * r1r[h] * a);
        }
#pragma unroll
        for (int i = kChunk - 1; i >= 0; --i) {
            u64 rs = 0ull;
#pragma unroll
            for (int h = 0; h < kH; ++h) {
                u[h] = fma2(q2[h], u[h], xv[i]);
                rs   = fma2(w[h], u[h], rs);
            }
            store_cs(od + i * (kD / 2),
                     add2(acc[i * kThreads + tid], rs));  // out written once
        }
    }
}

// ---------------------------------------------------------------------------
extern "C" void kernel_launch(void* const* d_in, const int* in_sizes, int n_in,
                              void* d_out, int out_size)
{
    const float* x   = (const float*)d_in[0];
    const float* ex  = (const float*)d_in[1];
    const float* re  = (const float*)d_in[2];
    const float* al  = (const float*)d_in[3];
    const float* da  = (const float*)d_in[4];
    const float* ral = (const float*)d_in[5];
    const float* rda = (const float*)d_in[6];
    float* out = (float*)d_out;

    ema_agg<<<kBlocks, kThreads>>>(x, al, da, ral, rda);

    // Kernel B with Programmatic Dependent Launch: overlaps its DRAM
    // prologue (x + weights) with kernel A; griddepcontrol.wait guards the
    // aggregate reads. If PDL is unsupported, semantics degrade to serial.
    cudaLaunchConfig_t cfg = {};
    cfg.gridDim  = dim3(kBlocks);
    cfg.blockDim = dim3(kThreads);
    cfg.dynamicSmemBytes = 0;
    cfg.stream = 0;
    cudaLaunchAttribute attrs[1];
    attrs[0].id = cudaLaunchAttributeProgrammaticStreamSerialization;
    attrs[0].val.programmaticStreamSerializationAllowed = 1;
    cfg.attrs = attrs;
    cfg.numAttrs = 1;
    cudaLaunchKernelEx(&cfg, ema_out, x, ex, re, al, da, ral, rda, out);
}